// round 3
// baseline (speedup 1.0000x reference)
#include <cuda_runtime.h>
#include <cstddef>

#define KC 16
#define NMAX 100000
#define E2MAX 3200000
#define BP_EPS 1e-12f

// Persistent scratch (device globals; no allocation allowed).
static __device__ float g_lmA[(size_t)E2MAX * KC];  // log2(messages) ping (204.8 MB)
static __device__ float g_lmB[(size_t)E2MAX * KC];  // log2(messages) pong (204.8 MB)
static __device__ float g_S[5][(size_t)NMAX * KC];  // node accumulators per iteration
static __device__ float g_psi[KC * KC];
static __device__ float g_acoef[KC];
static __device__ float g_off;
static __device__ int   g_fast;

__device__ __forceinline__ float ex2f(float x) {
    float y; asm("ex2.approx.f32 %0, %1;" : "=f"(y) : "f"(x)); return y;
}
__device__ __forceinline__ float lg2f_(float x) {
    float y; asm("lg2.approx.f32 %0, %1;" : "=f"(y) : "f"(x)); return y;
}
__device__ __forceinline__ void red_v4(float* p, float a, float b, float c, float d) {
    asm volatile("red.global.add.v4.f32 [%0], {%1, %2, %3, %4};"
                 :: "l"(p), "f"(a), "f"(b), "f"(c), "f"(d) : "memory");
}

// psi = exp(log_psi); detect diag-plus-constant structure for the fast path.
__global__ void prep_psi_kernel(const float* __restrict__ logpsi) {
    __shared__ float psi[KC * KC];
    int t = threadIdx.x;
    if (t < KC * KC) { float p = expf(logpsi[t]); psi[t] = p; g_psi[t] = p; }
    __syncthreads();
    if (t == 0) {
        float off = psi[1];
        int fast = 1;
        for (int i = 0; i < KC; i++)
            for (int j = 0; j < KC; j++)
                if (i != j && psi[i * KC + j] != off) fast = 0;
        g_fast = fast;
        g_off = off;
        for (int c = 0; c < KC; c++) g_acoef[c] = psi[c * KC + c] - off;
    }
}

// All 5 S buffers := log2(prior)  (read prior once, write 5x -> 32 MB, trivial)
__global__ void init_all_S_kernel(const float* __restrict__ prior, int n16) {
    int i = blockIdx.x * blockDim.x + threadIdx.x;
    if (i >= n16) return;
    float v = log2f(prior[i]);
    g_S[0][i] = v; g_S[1][i] = v; g_S[2][i] = v; g_S[3][i] = v; g_S[4][i] = v;
}

// Inject initial uniform messages into S[0]: S0[dst[e]][:] += log2(1/16) = -4.
__global__ void acc_uniform_kernel(const int* __restrict__ dst, int e2) {
    int e = blockIdx.x * blockDim.x + threadIdx.x;
    if (e >= e2) return;
    float* p = g_S[0] + (size_t)dst[e] * KC;
    red_v4(p + 0,  -4.f, -4.f, -4.f, -4.f);
    red_v4(p + 4,  -4.f, -4.f, -4.f, -4.f);
    red_v4(p + 8,  -4.f, -4.f, -4.f, -4.f);
    red_v4(p + 12, -4.f, -4.f, -4.f, -4.f);
}

// One BP iteration, one directed edge per thread.
// lm_new[e] = log2(normalize(max(2^(Sin[src[e]] - lm_old[rev[e]]), EPS) @ psi))
// and red-add lm_new[e] into Snext[dst[e]] (pre-initialized to log2 prior).
// FIRST: lm_old is implicitly uniform (-4), skip its read.
template <int FIRST, int AB>
__global__ void __launch_bounds__(256) update_kernel(
    const int* __restrict__ src, const int* __restrict__ dst, const int* __restrict__ rev,
    int sin_idx, int e2)
{
    __shared__ float s_psi[KC * KC];
    __shared__ float s_a[KC];
    __shared__ float s_off;
    __shared__ int   s_fast;
    int t = threadIdx.x;
    if (t < KC * KC) s_psi[t] = g_psi[t];
    if (t < KC) s_a[t] = g_acoef[t];
    if (t == 0) { s_off = g_off; s_fast = g_fast; }
    __syncthreads();

    int e = blockIdx.x * blockDim.x + t;
    if (e >= e2) return;

    const float* __restrict__ lm_old = AB ? g_lmA : g_lmB;
    float* __restrict__       lm_new = AB ? g_lmB : g_lmA;
    const float* __restrict__ Sin = g_S[sin_idx];
    float* __restrict__       Snext = g_S[sin_idx + 1];

    int s = src[e], d = dst[e];

    // reverse message (leave-one-out term)
    float lmr[KC];
    if (FIRST) {
        #pragma unroll
        for (int c = 0; c < KC; c++) lmr[c] = -4.f;
    } else {
        int er = rev[e];
        const float4* pr = reinterpret_cast<const float4*>(lm_old + (size_t)er * KC);
        #pragma unroll
        for (int q = 0; q < 4; q++) {
            float4 w = pr[q];
            lmr[4*q+0] = w.x; lmr[4*q+1] = w.y; lmr[4*q+2] = w.z; lmr[4*q+3] = w.w;
        }
    }

    // gather S row for src node
    const float4* pp = reinterpret_cast<const float4*>(Sin + (size_t)s * KC);
    float b[KC];
    float T = 0.f;
    #pragma unroll
    for (int q = 0; q < 4; q++) {
        float4 v = pp[q];
        float x0 = fmaxf(ex2f(v.x - lmr[4*q+0]), BP_EPS);
        float x1 = fmaxf(ex2f(v.y - lmr[4*q+1]), BP_EPS);
        float x2 = fmaxf(ex2f(v.z - lmr[4*q+2]), BP_EPS);
        float x3 = fmaxf(ex2f(v.w - lmr[4*q+3]), BP_EPS);
        b[4*q+0] = x0; b[4*q+1] = x1; b[4*q+2] = x2; b[4*q+3] = x3;
        T += x0 + x1 + x2 + x3;
    }

    float m[KC];
    float Z = 0.f;
    if (s_fast) {
        float oT = s_off * T;
        #pragma unroll
        for (int c = 0; c < KC; c++) {
            float v = fmaf(s_a[c], b[c], oT);
            m[c] = v; Z += v;
        }
    } else {
        #pragma unroll
        for (int c = 0; c < KC; c++) {
            float acc = 0.f;
            #pragma unroll
            for (int j = 0; j < KC; j++) acc = fmaf(b[j], s_psi[j * KC + c], acc);
            m[c] = acc; Z += acc;
        }
    }
    float lZ = lg2f_(Z);
    #pragma unroll
    for (int c = 0; c < KC; c++) m[c] = lg2f_(m[c]) - lZ;

    float4* po = reinterpret_cast<float4*>(lm_new + (size_t)e * KC);
    #pragma unroll
    for (int q = 0; q < 4; q++) {
        float4 v;
        v.x = m[4*q+0]; v.y = m[4*q+1]; v.z = m[4*q+2]; v.w = m[4*q+3];
        po[q] = v;
    }
    float* red_row = Snext + (size_t)d * KC;
    red_v4(red_row + 0,  m[0],  m[1],  m[2],  m[3]);
    red_v4(red_row + 4,  m[4],  m[5],  m[6],  m[7]);
    red_v4(red_row + 8,  m[8],  m[9],  m[10], m[11]);
    red_v4(red_row + 12, m[12], m[13], m[14], m[15]);
}

// beliefs: out = normalize(max(2^S, EPS))   (S already includes log2 prior)
__global__ void belief_kernel(float* __restrict__ out, int n) {
    int i = blockIdx.x * blockDim.x + threadIdx.x;
    if (i >= n) return;
    const float4* pp = reinterpret_cast<const float4*>(g_S[4] + (size_t)i * KC);
    float b[KC];
    float Z = 0.f;
    #pragma unroll
    for (int q = 0; q < 4; q++) {
        float4 v = pp[q];
        float x0 = fmaxf(ex2f(v.x), BP_EPS);
        float x1 = fmaxf(ex2f(v.y), BP_EPS);
        float x2 = fmaxf(ex2f(v.z), BP_EPS);
        float x3 = fmaxf(ex2f(v.w), BP_EPS);
        b[4*q+0] = x0; b[4*q+1] = x1; b[4*q+2] = x2; b[4*q+3] = x3;
        Z += x0 + x1 + x2 + x3;
    }
    float r = 1.f / Z;
    float4* po = reinterpret_cast<float4*>(out + (size_t)i * KC);
    #pragma unroll
    for (int q = 0; q < 4; q++) {
        float4 v;
        v.x = b[4*q+0] * r; v.y = b[4*q+1] * r; v.z = b[4*q+2] * r; v.w = b[4*q+3] * r;
        po[q] = v;
    }
}

extern "C" void kernel_launch(void* const* d_in, const int* in_sizes, int n_in,
                              void* d_out, int out_size) {
    const float* prior  = (const float*)d_in[0];
    const float* logpsi = (const float*)d_in[1];
    const int*   src    = (const int*)d_in[2];
    const int*   dst    = (const int*)d_in[3];
    const int*   rev    = (const int*)d_in[4];
    float* out = (float*)d_out;

    int n16 = in_sizes[0];      // n * 16
    int n   = n16 / KC;
    int e2  = in_sizes[2];      // directed edges

    int gb_n16 = (n16 + 255) / 256;
    int gb_e2  = (e2 + 255) / 256;
    int gb_n   = (n + 255) / 256;

    // launches #0..#2: prelude
    prep_psi_kernel<<<1, 256>>>(logpsi);
    init_all_S_kernel<<<gb_n16, 256>>>(prior, n16);
    acc_uniform_kernel<<<gb_e2, 256>>>(dst, e2);

    // launches #3..#6: the 4 BP iterations (ncu -s 5 lands on a steady update)
    update_kernel<1, 1><<<gb_e2, 256>>>(src, dst, rev, 0, e2);  // S0 -> S1, write lmB
    update_kernel<0, 0><<<gb_e2, 256>>>(src, dst, rev, 1, e2);  // S1 -> S2, lmB -> lmA
    update_kernel<0, 1><<<gb_e2, 256>>>(src, dst, rev, 2, e2);  // S2 -> S3, lmA -> lmB
    update_kernel<0, 0><<<gb_e2, 256>>>(src, dst, rev, 3, e2);  // S3 -> S4, lmB -> lmA

    belief_kernel<<<gb_n, 256>>>(out, n);
}

// round 4
// speedup vs baseline: 1.5472x; 1.5472x over previous
#include <cuda_runtime.h>
#include <cstddef>

#define KC 16
#define NMAX 100000
#define E2MAX 3200000
#define BP_EPS 1e-12f

// Persistent scratch (device globals; no allocation allowed).
static __device__ float g_lmA[(size_t)E2MAX * KC];  // log2(messages) ping (204.8 MB)
static __device__ float g_lmB[(size_t)E2MAX * KC];  // log2(messages) pong (204.8 MB)
static __device__ float g_S[5][(size_t)NMAX * KC];  // node accumulators per iteration
static __device__ int   g_deg[NMAX];                // in-degree
static __device__ float g_psi[KC * KC];
static __device__ float g_acoef[KC];
static __device__ float g_off;
static __device__ int   g_fast;

__device__ __forceinline__ float ex2f(float x) {
    float y; asm("ex2.approx.f32 %0, %1;" : "=f"(y) : "f"(x)); return y;
}
__device__ __forceinline__ float lg2f_(float x) {
    float y; asm("lg2.approx.f32 %0, %1;" : "=f"(y) : "f"(x)); return y;
}
__device__ __forceinline__ void red_v4(float* p, float a, float b, float c, float d) {
    asm volatile("red.global.add.v4.f32 [%0], {%1, %2, %3, %4};"
                 :: "l"(p), "f"(a), "f"(b), "f"(c), "f"(d) : "memory");
}
// sum across the 4 lanes of an aligned quad
__device__ __forceinline__ float quad_sum(float v) {
    v += __shfl_xor_sync(0xFFFFFFFFu, v, 1);
    v += __shfl_xor_sync(0xFFFFFFFFu, v, 2);
    return v;
}

// psi = exp(log_psi); detect diag-plus-constant structure for the fast path.
__global__ void prep_psi_kernel(const float* __restrict__ logpsi) {
    __shared__ float psi[KC * KC];
    int t = threadIdx.x;
    if (t < KC * KC) { float p = expf(logpsi[t]); psi[t] = p; g_psi[t] = p; }
    __syncthreads();
    if (t == 0) {
        float off = psi[1];
        int fast = 1;
        for (int i = 0; i < KC; i++)
            for (int j = 0; j < KC; j++)
                if (i != j && psi[i * KC + j] != off) fast = 0;
        g_fast = fast;
        g_off = off;
        for (int c = 0; c < KC; c++) g_acoef[c] = psi[c * KC + c] - off;
    }
}

__global__ void zero_deg_kernel(int n) {
    int i = blockIdx.x * blockDim.x + threadIdx.x;
    if (i < n) g_deg[i] = 0;
}

__global__ void deg_hist_kernel(const int* __restrict__ dst, int e2) {
    int e = blockIdx.x * blockDim.x + threadIdx.x;
    if (e < e2) atomicAdd(&g_deg[dst[e]], 1);
}

// S[0] := log2(prior) + deg*(-4);  S[1..4] := log2(prior)
__global__ void init_all_S_kernel(const float* __restrict__ prior, int n16) {
    int i = blockIdx.x * blockDim.x + threadIdx.x;
    if (i >= n16) return;
    float v = log2f(prior[i]);
    int node = i >> 4;
    g_S[0][i] = fmaf((float)g_deg[node], -4.f, v);
    g_S[1][i] = v; g_S[2][i] = v; g_S[3][i] = v; g_S[4][i] = v;
}

// One BP iteration: 4 threads (one aligned quad) per directed edge, each lane
// owns 4 classes. lm_new[e] = log2(normalize(max(2^(Sin[src]-lm_old[rev]),EPS)@psi))
// and red-add into Snext[dst] (pre-initialized to log2 prior).
template <int FIRST, int AB>
__global__ void __launch_bounds__(256) update_kernel(
    const int* __restrict__ src, const int* __restrict__ dst, const int* __restrict__ rev,
    int sin_idx, int e2)
{
    __shared__ float s_psi[KC * KC];
    __shared__ float s_a[KC];
    __shared__ float s_off;
    __shared__ int   s_fast;
    int t = threadIdx.x;
    if (t < KC * KC) s_psi[t] = g_psi[t];
    if (t < KC) s_a[t] = g_acoef[t];
    if (t == 0) { s_off = g_off; s_fast = g_fast; }
    __syncthreads();

    int gt  = blockIdx.x * blockDim.x + t;
    int e   = gt >> 2;         // edge index
    int sub = t & 3;           // class-group within edge (aligned quad)
    if (e >= e2) return;

    const float* __restrict__ lm_old = AB ? g_lmA : g_lmB;
    float* __restrict__       lm_new = AB ? g_lmB : g_lmA;
    const float* __restrict__ Sin   = g_S[sin_idx];
    float* __restrict__       Snext = g_S[sin_idx + 1];

    int s = src[e], d = dst[e];

    // reverse message slice (leave-one-out term), 4 classes
    float4 lmr;
    if (FIRST) {
        lmr = make_float4(-4.f, -4.f, -4.f, -4.f);
    } else {
        int er = rev[e];
        lmr = *reinterpret_cast<const float4*>(lm_old + (size_t)er * KC + sub * 4);
    }

    // gather S slice for src node (4 consecutive floats; quad covers the row)
    float4 P = *reinterpret_cast<const float4*>(Sin + (size_t)s * KC + sub * 4);

    float b0 = fmaxf(ex2f(P.x - lmr.x), BP_EPS);
    float b1 = fmaxf(ex2f(P.y - lmr.y), BP_EPS);
    float b2 = fmaxf(ex2f(P.z - lmr.z), BP_EPS);
    float b3 = fmaxf(ex2f(P.w - lmr.w), BP_EPS);
    float T = quad_sum(b0 + b1 + b2 + b3);

    float m0, m1, m2, m3;
    if (s_fast) {
        float oT = s_off * T;
        m0 = fmaf(s_a[sub * 4 + 0], b0, oT);
        m1 = fmaf(s_a[sub * 4 + 1], b1, oT);
        m2 = fmaf(s_a[sub * 4 + 2], b2, oT);
        m3 = fmaf(s_a[sub * 4 + 3], b3, oT);
    } else {
        // generic psi: gather all 16 b values from the quad via shuffles
        float bl[4] = {b0, b1, b2, b3};
        float acc[4] = {0.f, 0.f, 0.f, 0.f};
        int base = t & ~3;  // not needed for shfl_sync lane math below (uses full warp id)
        (void)base;
        #pragma unroll
        for (int j = 0; j < KC; j++) {
            int owner_sub = j >> 2;
            float bj = __shfl_sync(0xFFFFFFFFu, bl[j & 3], (t & ~3 & 31) | owner_sub, 32);
            // lane index within warp: ((lane & ~3) | owner_sub)
            #pragma unroll
            for (int c = 0; c < 4; c++)
                acc[c] = fmaf(bj, s_psi[j * KC + sub * 4 + c], acc[c]);
        }
        m0 = acc[0]; m1 = acc[1]; m2 = acc[2]; m3 = acc[3];
    }
    float Z = quad_sum(m0 + m1 + m2 + m3);
    float lZ = lg2f_(Z);
    m0 = lg2f_(m0) - lZ;
    m1 = lg2f_(m1) - lZ;
    m2 = lg2f_(m2) - lZ;
    m3 = lg2f_(m3) - lZ;

    *reinterpret_cast<float4*>(lm_new + (size_t)e * KC + sub * 4) =
        make_float4(m0, m1, m2, m3);
    red_v4(Snext + (size_t)d * KC + sub * 4, m0, m1, m2, m3);
}

// beliefs: out = normalize(max(2^S4, EPS)); quad per node.
__global__ void belief_kernel(float* __restrict__ out, int n) {
    int gt  = blockIdx.x * blockDim.x + threadIdx.x;
    int i   = gt >> 2;
    int sub = threadIdx.x & 3;
    if (i >= n) return;
    float4 v = *reinterpret_cast<const float4*>(g_S[4] + (size_t)i * KC + sub * 4);
    float x0 = fmaxf(ex2f(v.x), BP_EPS);
    float x1 = fmaxf(ex2f(v.y), BP_EPS);
    float x2 = fmaxf(ex2f(v.z), BP_EPS);
    float x3 = fmaxf(ex2f(v.w), BP_EPS);
    float Z = quad_sum(x0 + x1 + x2 + x3);
    float r = 1.f / Z;
    *reinterpret_cast<float4*>(out + (size_t)i * KC + sub * 4) =
        make_float4(x0 * r, x1 * r, x2 * r, x3 * r);
}

extern "C" void kernel_launch(void* const* d_in, const int* in_sizes, int n_in,
                              void* d_out, int out_size) {
    const float* prior  = (const float*)d_in[0];
    const float* logpsi = (const float*)d_in[1];
    const int*   src    = (const int*)d_in[2];
    const int*   dst    = (const int*)d_in[3];
    const int*   rev    = (const int*)d_in[4];
    float* out = (float*)d_out;

    int n16 = in_sizes[0];      // n * 16
    int n   = n16 / KC;
    int e2  = in_sizes[2];      // directed edges

    int gb_n16 = (n16 + 255) / 256;
    int gb_e2  = (e2 + 255) / 256;
    int gb_q   = (e2 * 4 + 255) / 256;   // quad-per-edge grids
    int gb_nq  = (n * 4 + 255) / 256;
    int gb_n   = (n + 255) / 256;

    // #0..#3: prelude
    prep_psi_kernel<<<1, 256>>>(logpsi);
    zero_deg_kernel<<<gb_n, 256>>>(n);
    deg_hist_kernel<<<gb_e2, 256>>>(dst, e2);
    init_all_S_kernel<<<gb_n16, 256>>>(prior, n16);

    // #4..#7: the 4 BP iterations (ncu -s 5 lands on a steady update)
    update_kernel<1, 1><<<gb_q, 256>>>(src, dst, rev, 0, e2);  // S0 -> S1, write lmB
    update_kernel<0, 0><<<gb_q, 256>>>(src, dst, rev, 1, e2);  // S1 -> S2, lmB -> lmA
    update_kernel<0, 1><<<gb_q, 256>>>(src, dst, rev, 2, e2);  // S2 -> S3, lmA -> lmB
    update_kernel<0, 0><<<gb_q, 256>>>(src, dst, rev, 3, e2);  // S3 -> S4, lmB -> lmA

    belief_kernel<<<gb_nq, 256>>>(out, n);
}

// round 5
// speedup vs baseline: 1.8247x; 1.1794x over previous
#include <cuda_runtime.h>
#include <cstddef>

#define KC 16
#define NMAX 100000
#define E2MAX 3200000
#define BP_EPS 1e-12f

// Persistent scratch (device globals; no allocation allowed).
static __device__ float g_lmA[(size_t)E2MAX * KC];  // log2(messages) ping (204.8 MB)
static __device__ float g_lmB[(size_t)E2MAX * KC];  // log2(messages) pong (204.8 MB)
static __device__ float g_S[5][(size_t)NMAX * KC];  // node accumulators (use [1..4])
static __device__ int   g_deg[NMAX];                // in-degree
static __device__ float g_psi[KC * KC];
static __device__ float g_acoef[KC];
static __device__ float g_off;
static __device__ int   g_fast;

__device__ __forceinline__ float ex2f(float x) {
    float y; asm("ex2.approx.f32 %0, %1;" : "=f"(y) : "f"(x)); return y;
}
__device__ __forceinline__ float lg2f_(float x) {
    float y; asm("lg2.approx.f32 %0, %1;" : "=f"(y) : "f"(x)); return y;
}
__device__ __forceinline__ void red_v4(float* p, float a, float b, float c, float d) {
    asm volatile("red.global.add.v4.f32 [%0], {%1, %2, %3, %4};"
                 :: "l"(p), "f"(a), "f"(b), "f"(c), "f"(d) : "memory");
}
// sum across the 4 lanes of an aligned quad
__device__ __forceinline__ float quad_sum(float v) {
    v += __shfl_xor_sync(0xFFFFFFFFu, v, 1);
    v += __shfl_xor_sync(0xFFFFFFFFu, v, 2);
    return v;
}

// k0: block 0 computes psi tables; all blocks zero the degree histogram.
__global__ void prep_kernel(const float* __restrict__ logpsi, int n) {
    int t = threadIdx.x;
    if (blockIdx.x == 0) {
        __shared__ float psi[KC * KC];
        if (t < KC * KC) { float p = expf(logpsi[t]); psi[t] = p; g_psi[t] = p; }
        __syncthreads();
        if (t == 0) {
            float off = psi[1];
            int fast = 1;
            for (int i = 0; i < KC; i++)
                for (int j = 0; j < KC; j++)
                    if (i != j && psi[i * KC + j] != off) fast = 0;
            g_fast = fast;
            g_off = off;
            for (int c = 0; c < KC; c++) g_acoef[c] = psi[c * KC + c] - off;
        }
    }
    int i = blockIdx.x * blockDim.x + t;
    if (i < n) g_deg[i] = 0;
}

// k1: degree histogram + init S[1..4] = log2(prior)  (independent writes)
__global__ void hist_init_kernel(const int* __restrict__ dst,
                                 const float* __restrict__ prior, int e2, int n16) {
    int i = blockIdx.x * blockDim.x + threadIdx.x;
    if (i < e2) atomicAdd(&g_deg[dst[i]], 1);
    if (i < n16) {
        float v = log2f(prior[i]);
        g_S[1][i] = v; g_S[2][i] = v; g_S[3][i] = v; g_S[4][i] = v;
    }
}

// Message body: given b-slice (4 classes) already clamped, produce normalized
// log2 message slice. T = quad sum of b.
__device__ __forceinline__ void msg_from_b(
    float b0, float b1, float b2, float b3, int sub,
    const float* __restrict__ s_a, const float* __restrict__ s_psi,
    int fast, float off, int t,
    float& m0, float& m1, float& m2, float& m3)
{
    float T = quad_sum(b0 + b1 + b2 + b3);
    if (fast) {
        float oT = off * T;
        m0 = fmaf(s_a[sub * 4 + 0], b0, oT);
        m1 = fmaf(s_a[sub * 4 + 1], b1, oT);
        m2 = fmaf(s_a[sub * 4 + 2], b2, oT);
        m3 = fmaf(s_a[sub * 4 + 3], b3, oT);
    } else {
        float bl[4] = {b0, b1, b2, b3};
        float acc[4] = {0.f, 0.f, 0.f, 0.f};
        #pragma unroll
        for (int j = 0; j < KC; j++) {
            int owner_sub = j >> 2;
            float bj = __shfl_sync(0xFFFFFFFFu, bl[j & 3], ((t & 31) & ~3) | owner_sub, 32);
            #pragma unroll
            for (int c = 0; c < 4; c++)
                acc[c] = fmaf(bj, s_psi[j * KC + sub * 4 + c], acc[c]);
        }
        m0 = acc[0]; m1 = acc[1]; m2 = acc[2]; m3 = acc[3];
    }
    float Z = quad_sum(m0 + m1 + m2 + m3);
    float lZ = lg2f_(Z);
    m0 = lg2f_(m0) - lZ;
    m1 = lg2f_(m1) - lZ;
    m2 = lg2f_(m2) - lZ;
    m3 = lg2f_(m3) - lZ;
}

#define LOAD_TABLES() \
    __shared__ float s_psi[KC * KC]; \
    __shared__ float s_a[KC]; \
    __shared__ float s_off_sh; \
    __shared__ int   s_fast_sh; \
    { int tt = threadIdx.x; \
      if (tt < KC * KC) s_psi[tt] = g_psi[tt]; \
      if (tt < KC) s_a[tt] = g_acoef[tt]; \
      if (tt == 0) { s_off_sh = g_off; s_fast_sh = g_fast; } } \
    __syncthreads();

// k2: first BP iteration. Pair (q, q+E) per quad. Messages are uniform, so
// b_e0 = max(prior[s]*2^(4-4*deg_in[s]), EPS) (identically 16^(1-deg)).
// Writes lmB rows q, q+E; REDs into S[1].
__global__ void __launch_bounds__(256) update_first_kernel(
    const int* __restrict__ src, const int* __restrict__ dst,
    const float* __restrict__ prior, int E)
{
    LOAD_TABLES();
    int t = threadIdx.x;
    int gt = blockIdx.x * blockDim.x + t;
    int q = gt >> 2, sub = t & 3;
    int valid = q < E;
    if (!valid) q = E - 1;

    int s = src[q], d = dst[q];
    float ws = ex2f(fmaf((float)g_deg[s], -4.f, 4.f));
    float wd = ex2f(fmaf((float)g_deg[d], -4.f, 4.f));
    float4 Ps = *reinterpret_cast<const float4*>(prior + (size_t)s * KC + sub * 4);
    float4 Pd = *reinterpret_cast<const float4*>(prior + (size_t)d * KC + sub * 4);

    const int fast = s_fast_sh; const float off = s_off_sh;

    // edge e0 = q: s -> d
    float a0 = fmaxf(Ps.x * ws, BP_EPS), a1 = fmaxf(Ps.y * ws, BP_EPS);
    float a2 = fmaxf(Ps.z * ws, BP_EPS), a3 = fmaxf(Ps.w * ws, BP_EPS);
    float m0, m1, m2, m3;
    msg_from_b(a0, a1, a2, a3, sub, s_a, s_psi, fast, off, t, m0, m1, m2, m3);

    // edge e1 = q+E: d -> s
    float c0 = fmaxf(Pd.x * wd, BP_EPS), c1 = fmaxf(Pd.y * wd, BP_EPS);
    float c2 = fmaxf(Pd.z * wd, BP_EPS), c3 = fmaxf(Pd.w * wd, BP_EPS);
    float r0, r1, r2, r3;
    msg_from_b(c0, c1, c2, c3, sub, s_a, s_psi, fast, off, t, r0, r1, r2, r3);

    if (valid) {
        *reinterpret_cast<float4*>(g_lmB + (size_t)q * KC + sub * 4) =
            make_float4(m0, m1, m2, m3);
        *reinterpret_cast<float4*>(g_lmB + ((size_t)q + E) * KC + sub * 4) =
            make_float4(r0, r1, r2, r3);
        red_v4(g_S[1] + (size_t)d * KC + sub * 4, m0, m1, m2, m3);
        red_v4(g_S[1] + (size_t)s * KC + sub * 4, r0, r1, r2, r3);
    }
}

// Steady BP iteration. Pair (q, q+E) per quad; the two edges are each other's
// reverse. AB=0: old=lmB,new=lmA; AB=1: old=lmA,new=lmB. LAST: skip lm store.
template <int AB, int LAST>
__global__ void __launch_bounds__(256) update_kernel(
    const int* __restrict__ src, const int* __restrict__ dst, int sin_idx, int E)
{
    LOAD_TABLES();
    int t = threadIdx.x;
    int gt = blockIdx.x * blockDim.x + t;
    int q = gt >> 2, sub = t & 3;
    int valid = q < E;
    if (!valid) q = E - 1;

    const float* __restrict__ lm_old = AB ? g_lmA : g_lmB;
    float* __restrict__       lm_new = AB ? g_lmB : g_lmA;
    const float* __restrict__ Sin   = g_S[sin_idx];
    float* __restrict__       Snext = g_S[sin_idx + 1];

    int s = src[q], d = dst[q];

    // old messages of the pair (each is the other's leave-one-out term)
    float4 lm0 = *reinterpret_cast<const float4*>(lm_old + (size_t)q * KC + sub * 4);
    float4 lm1 = *reinterpret_cast<const float4*>(lm_old + ((size_t)q + E) * KC + sub * 4);
    float4 Ss = *reinterpret_cast<const float4*>(Sin + (size_t)s * KC + sub * 4);
    float4 Sd = *reinterpret_cast<const float4*>(Sin + (size_t)d * KC + sub * 4);

    const int fast = s_fast_sh; const float off = s_off_sh;

    // edge e0 = q (s->d): excludes reverse message lm1
    float a0 = fmaxf(ex2f(Ss.x - lm1.x), BP_EPS);
    float a1 = fmaxf(ex2f(Ss.y - lm1.y), BP_EPS);
    float a2 = fmaxf(ex2f(Ss.z - lm1.z), BP_EPS);
    float a3 = fmaxf(ex2f(Ss.w - lm1.w), BP_EPS);
    float m0, m1, m2, m3;
    msg_from_b(a0, a1, a2, a3, sub, s_a, s_psi, fast, off, t, m0, m1, m2, m3);

    // edge e1 = q+E (d->s): excludes reverse message lm0
    float c0 = fmaxf(ex2f(Sd.x - lm0.x), BP_EPS);
    float c1 = fmaxf(ex2f(Sd.y - lm0.y), BP_EPS);
    float c2 = fmaxf(ex2f(Sd.z - lm0.z), BP_EPS);
    float c3 = fmaxf(ex2f(Sd.w - lm0.w), BP_EPS);
    float r0, r1, r2, r3;
    msg_from_b(c0, c1, c2, c3, sub, s_a, s_psi, fast, off, t, r0, r1, r2, r3);

    if (valid) {
        if (!LAST) {
            *reinterpret_cast<float4*>(lm_new + (size_t)q * KC + sub * 4) =
                make_float4(m0, m1, m2, m3);
            *reinterpret_cast<float4*>(lm_new + ((size_t)q + E) * KC + sub * 4) =
                make_float4(r0, r1, r2, r3);
        }
        red_v4(Snext + (size_t)d * KC + sub * 4, m0, m1, m2, m3);
        red_v4(Snext + (size_t)s * KC + sub * 4, r0, r1, r2, r3);
    }
}

// beliefs: out = normalize(max(2^S4, EPS)); quad per node.
__global__ void belief_kernel(float* __restrict__ out, int n) {
    int gt  = blockIdx.x * blockDim.x + threadIdx.x;
    int i   = gt >> 2;
    int sub = threadIdx.x & 3;
    if (i >= n) return;
    float4 v = *reinterpret_cast<const float4*>(g_S[4] + (size_t)i * KC + sub * 4);
    float x0 = fmaxf(ex2f(v.x), BP_EPS);
    float x1 = fmaxf(ex2f(v.y), BP_EPS);
    float x2 = fmaxf(ex2f(v.z), BP_EPS);
    float x3 = fmaxf(ex2f(v.w), BP_EPS);
    float Z = quad_sum(x0 + x1 + x2 + x3);
    float r = 1.f / Z;
    *reinterpret_cast<float4*>(out + (size_t)i * KC + sub * 4) =
        make_float4(x0 * r, x1 * r, x2 * r, x3 * r);
}

extern "C" void kernel_launch(void* const* d_in, const int* in_sizes, int n_in,
                              void* d_out, int out_size) {
    const float* prior  = (const float*)d_in[0];
    const float* logpsi = (const float*)d_in[1];
    const int*   src    = (const int*)d_in[2];
    const int*   dst    = (const int*)d_in[3];
    float* out = (float*)d_out;

    int n16 = in_sizes[0];      // n * 16
    int n   = n16 / KC;
    int e2  = in_sizes[2];      // directed edges
    int E   = e2 / 2;           // undirected pairs

    int gb_n    = (n + 255) / 256;
    int gb_e2   = (e2 + 255) / 256;
    int gb_pair = (E * 4 + 255) / 256;   // quad-per-pair grid
    int gb_nq   = (n * 4 + 255) / 256;

    // #0, #1: prelude
    prep_kernel<<<gb_n, 256>>>(logpsi, n);
    hist_init_kernel<<<gb_e2, 256>>>(dst, prior, e2, n16);

    // #2: iteration 1 (uniform messages -> from prior+deg), writes lmB, S1
    update_first_kernel<<<gb_pair, 256>>>(src, dst, prior, E);
    // #3: iteration 2 (steady; ncu capture lands here), lmB -> lmA, S1 -> S2
    update_kernel<0, 0><<<gb_pair, 256>>>(src, dst, 1, E);
    // #4: iteration 3, lmA -> lmB, S2 -> S3
    update_kernel<1, 0><<<gb_pair, 256>>>(src, dst, 2, E);
    // #5: iteration 4 (no message store needed), lmB -> (none), S3 -> S4
    update_kernel<0, 1><<<gb_pair, 256>>>(src, dst, 3, E);

    // #6: beliefs
    belief_kernel<<<gb_nq, 256>>>(out, n);
}